// round 16
// baseline (speedup 1.0000x reference)
#include <cuda_runtime.h>
#include <cuda_bf16.h>
#include <cstdint>

// x: (128, 512, 14, 14) fp32 ; W: (20, 512) fp32
#define NT   128
#define CCH  512
#define HWS  196
#define TT   8
#define NN   16
#define HH   4
#define KK   5
#define OO   20
#define BB   3136   // NN * HWS

// scratch: softmax weights, layout [h][t][k][B]
__device__ float g_weights[(size_t)HH * TT * KK * BB];
#define GW_IDX(h, t, k, b) ((((size_t)(h) * TT + (t)) * KK + (k)) * BB + (b))

// ---------------- kernel 1: TF32 tensor-core logits + softmax ---------------
#define KC      32
#define NCHUNK  16
#define NBUF    2
#define APITCH  104
#define ABUF    (KC * APITCH)
#define WTP     20
#define SMEM1_BYTES ((NBUF * ABUF + CCH * WTP + 16) * 4)   // 67648 (16f guard)

__device__ __forceinline__ uint32_t smem_u32(const void* p) {
    uint32_t a;
    asm("{ .reg .u64 t; cvta.to.shared.u64 t, %1; cvt.u32.u64 %0, t; }"
        : "=r"(a) : "l"(p));
    return a;
}

#define MMA_TF32(d, a0, a1, a2, a3, b0, b1)                                   \
    asm volatile("mma.sync.aligned.m16n8k8.row.col.f32.tf32.tf32.f32 "        \
                 "{%0,%1,%2,%3}, {%4,%5,%6,%7}, {%8,%9}, {%0,%1,%2,%3};"      \
                 : "+f"(d[0]), "+f"(d[1]), "+f"(d[2]), "+f"(d[3])             \
                 : "r"(a0), "r"(a1), "r"(a2), "r"(a3), "r"(b0), "r"(b1))

#define CP16(daddr, saddr)                                                    \
    asm volatile("cp.async.cg.shared.global [%0], [%1], 16;"                  \
                 :: "r"(daddr), "l"((const void*)(saddr)) : "memory")

__global__ void __launch_bounds__(256)
weights_mma_kernel(const float* __restrict__ x, const float* __restrict__ W)
{
    extern __shared__ float smem[];
    float* Abuf = smem;                    // [2][KC][APITCH]
    float* Wt   = smem + NBUF * ABUF;      // [512][20] (+guard)

    const int tid  = threadIdx.x;
    const int bid  = blockIdx.x;
    const int nt   = bid >> 1;             // image 0..127
    const int half = bid & 1;
    const int off  = half * 96;
    const int nsp  = half ? 100 : 96;
    const int nf4  = half ? 25 : 24;
    const int ntiles = half ? 7 : 6;

    const int w  = tid >> 5;
    const int l  = tid & 31;
    const int lg = l >> 2;
    const int lc = l & 3;

    // stage W transposed (raw fp32; mma HW truncates to tf32)
    for (int i = tid; i < OO * CCH; i += 256) {
        const int n = i >> 9, k = i & (CCH - 1);
        Wt[k * WTP + n] = W[i];
    }

    const float* xbase = x + (size_t)nt * CCH * HWS + off;
    const uint32_t abase_u32 = smem_u32(Abuf);

    // precompute per-thread cp.async slot offsets ONCE (kills per-chunk IDIV)
    // slots: f = tid, tid+256, tid+512 (always < KC*nf4), plus for half1
    // a 4th slot f = tid+768 valid when tid < KC*25-768 = 32.
    int nslots = (half && tid < 32) ? 4 : 3;
    size_t goff[4];                         // gmem float offset within chunk
    uint32_t soff[4];                       // smem byte offset within buffer
#pragma unroll
    for (int j = 0; j < 4; ++j) {
        const int f = tid + j * 256;
        const int c = f / nf4;              // computed once (runtime div, OK)
        const int i = f - c * nf4;
        goff[j] = (size_t)c * HWS + 4 * i;
        soff[j] = (uint32_t)((c * APITCH + 4 * i) * 4);
    }

    auto stage = [&](int ck) {
        const float* src = xbase + (size_t)ck * KC * HWS;
        const uint32_t dst0 = abase_u32 + (ck & (NBUF - 1)) * (ABUF * 4);
        CP16(dst0 + soff[0], src + goff[0]);
        CP16(dst0 + soff[1], src + goff[1]);
        CP16(dst0 + soff[2], src + goff[2]);
        if (nslots == 4) CP16(dst0 + soff[3], src + goff[3]);
        asm volatile("cp.async.commit_group;" ::: "memory");
    };

    const bool tvalid = (w < ntiles);
    const int sp0 = 16 * w + lg;
    const int spa = min(sp0, APITCH - 1);
    const int spb = min(sp0 + 8, APITCH - 1);

    float d[3][4];
#pragma unroll
    for (int nf = 0; nf < 3; ++nf)
#pragma unroll
        for (int r = 0; r < 4; ++r) d[nf][r] = 0.f;

    stage(0); stage(1);

    for (int ck = 0; ck < NCHUNK; ++ck) {
        if (ck < NCHUNK - 1) {
            asm volatile("cp.async.wait_group 1;" ::: "memory");
        } else {
            asm volatile("cp.async.wait_group 0;" ::: "memory");
        }
        __syncthreads();

        const float* Ab = Abuf + (ck & (NBUF - 1)) * ABUF;
#pragma unroll
        for (int k8 = 0; k8 < KC / 8; ++k8) {
            const int kl = k8 * 8;
            const int kg = ck * KC + kl + lc;
            uint32_t bfr[3][2];
#pragma unroll
            for (int nf = 0; nf < 3; ++nf) {
                bfr[nf][0] = __float_as_uint(Wt[kg * WTP + 8 * nf + lg]);
                bfr[nf][1] = __float_as_uint(Wt[(kg + 4) * WTP + 8 * nf + lg]);
            }
            if (tvalid) {
                const float* r0 = Ab + (kl + lc) * APITCH;
                const float* r4 = Ab + (kl + lc + 4) * APITCH;
                const uint32_t a0 = __float_as_uint(r0[spa]);
                const uint32_t a1 = __float_as_uint(r0[spb]);
                const uint32_t a2 = __float_as_uint(r4[spa]);
                const uint32_t a3 = __float_as_uint(r4[spb]);
#pragma unroll
                for (int nf = 0; nf < 3; ++nf)
                    MMA_TF32(d[nf], a0, a1, a2, a3, bfr[nf][0], bfr[nf][1]);
            }
        }
        __syncthreads();
        if (ck + 2 < NCHUNK) stage(ck + 2);
    }

    // exchange D through smem: Dx[112][24]
    float* Dx = smem;
    if (tvalid) {
        const int r = 16 * w + lg;
#pragma unroll
        for (int nf = 0; nf < 3; ++nf) {
            const int col = nf * 8 + 2 * lc;
            Dx[r * 24 + col]           = d[nf][0];
            Dx[r * 24 + col + 1]       = d[nf][1];
            Dx[(r + 8) * 24 + col]     = d[nf][2];
            Dx[(r + 8) * 24 + col + 1] = d[nf][3];
        }
    }
    __syncthreads();

    const int t_  = nt & (TT - 1);
    const int n_i = nt >> 3;
    for (int s = tid; s < nsp; s += 256) {
        const float* row = Dx + s * 24;
        const int b = n_i * HWS + off + s;
#pragma unroll
        for (int h = 0; h < HH; ++h) {
            float lo[KK];
#pragma unroll
            for (int k = 0; k < KK; ++k) lo[k] = row[h * KK + k];
            float m = lo[0];
#pragma unroll
            for (int k = 1; k < KK; ++k) m = fmaxf(m, lo[k]);
            float e[KK], sum = 0.f;
#pragma unroll
            for (int k = 0; k < KK; ++k) { e[k] = __expf(lo[k] - m); sum += e[k]; }
            const float inv = 1.f / sum;
#pragma unroll
            for (int k = 0; k < KK; ++k)
                g_weights[GW_IDX(h, t_, k, b)] = e[k] * inv;
        }
    }
}

// ---------------- kernel 2: causal 5-tap combine, lean float4 ---------------
// grid = (n_i : 16, ct : 64) -> 1024 CTAs; block = 196 = 49 f4-groups x 4
// channel-lanes; each lane owns ONE channel pair (no outer cp loop).
// Per thread: 16 LDG.128 (x) + 40 LDG.128 (weights, lane-broadcast, L1-hot)
// + 16 STG.128 for 256 outputs.
__global__ void __launch_bounds__(196)
combine_kernel(const float* __restrict__ x, float* __restrict__ out)
{
    const int n_i = blockIdx.x;
    const int ct  = blockIdx.y;           // 8-channel tile (64 tiles)
    const int h   = ct >> 4;              // head = (ct*8)/128

    const int tid = threadIdx.x;
    const int g   = tid % 49;             // float4 group: sp = 4g
    const int cl  = tid / 49;             // channel lane 0..3
    const int b0  = n_i * HWS + 4 * g;
    const int c0  = ct * 8 + cl * 2;      // this lane's channel pair

    const size_t tstride = (size_t)CCH * HWS;
    const size_t base = (size_t)n_i * TT * CCH * HWS + (size_t)c0 * HWS + 4 * g;

    float4 xv0[TT], xv1[TT];
#pragma unroll
    for (int t = 0; t < TT; ++t)
        xv0[t] = *reinterpret_cast<const float4*>(x + base + (size_t)t * tstride);
#pragma unroll
    for (int t = 0; t < TT; ++t)
        xv1[t] = *reinterpret_cast<const float4*>(x + base + HWS + (size_t)t * tstride);

#pragma unroll
    for (int t = 0; t < TT; ++t) {
        float4 a0 = make_float4(0.f, 0.f, 0.f, 0.f);
        float4 a1 = make_float4(0.f, 0.f, 0.f, 0.f);
#pragma unroll
        for (int k = 0; k < KK; ++k) {
            const int src = t + k - 4;               // causal left pad
            if (src >= 0) {
                const float4 w4 = *reinterpret_cast<const float4*>(
                    &g_weights[GW_IDX(h, t, k, b0)]);
                a0.x = fmaf(w4.x, xv0[src].x, a0.x);
                a0.y = fmaf(w4.y, xv0[src].y, a0.y);
                a0.z = fmaf(w4.z, xv0[src].z, a0.z);
                a0.w = fmaf(w4.w, xv0[src].w, a0.w);
                a1.x = fmaf(w4.x, xv1[src].x, a1.x);
                a1.y = fmaf(w4.y, xv1[src].y, a1.y);
                a1.z = fmaf(w4.z, xv1[src].z, a1.z);
                a1.w = fmaf(w4.w, xv1[src].w, a1.w);
            }
        }
        *reinterpret_cast<float4*>(out + base + (size_t)t * tstride) = a0;
        *reinterpret_cast<float4*>(out + base + HWS + (size_t)t * tstride) = a1;
    }
}

// ---------------------------------------------------------------------------
extern "C" void kernel_launch(void* const* d_in, const int* in_sizes, int n_in,
                              void* d_out, int out_size)
{
    const float* x = (const float*)d_in[0];
    const float* W = (const float*)d_in[1];
    float* out = (float*)d_out;

    cudaFuncSetAttribute(weights_mma_kernel,
                         cudaFuncAttributeMaxDynamicSharedMemorySize, SMEM1_BYTES);

    weights_mma_kernel<<<2 * NT, 256, SMEM1_BYTES>>>(x, W);
    combine_kernel<<<dim3(NN, 64), 196>>>(x, out);
}